// round 5
// baseline (speedup 1.0000x reference)
#include <cuda_runtime.h>
#include <math.h>

#define NN 50000
#define NE 600000
#define HH 128
#define EDD 16
#define TDD 32

#define ET 64      // edges per block (E1/E2)
#define PC_NB 8
#define PH_NB 16
#define PH_PAD 20

static_assert(NN % PC_NB == 0, "precompute exact");
static_assert(NN % PH_NB == 0, "node tile exact");
static_assert(NE % ET == 0, "edge tile exact");

// ---------------- device scratch ----------------
__device__ float g_A1[NN * HH];
__device__ float g_A2[NN * HH];
__device__ float g_B1[NN * HH];
__device__ float g_B2[NN * HH];
__device__ float g_msg[NN * HH];
__device__ float g_coord[NN * 3];
__device__ int   g_is64;

typedef unsigned long long u64;

__device__ __forceinline__ u64 pk(float lo, float hi) {
    u64 r; asm("mov.b64 %0,{%1,%2};" : "=l"(r) : "f"(lo), "f"(hi)); return r;
}
__device__ __forceinline__ void upk(float& lo, float& hi, u64 v) {
    asm("mov.b64 {%0,%1},%2;" : "=f"(lo), "=f"(hi) : "l"(v));
}
__device__ __forceinline__ u64 f2fma(u64 a, u64 b, u64 c) {
    u64 d; asm("fma.rn.f32x2 %0,%1,%2,%3;" : "=l"(d) : "l"(a), "l"(b), "l"(c)); return d;
}
__device__ __forceinline__ u64 f2add(u64 a, u64 b) {
    u64 d; asm("add.rn.f32x2 %0,%1,%2;" : "=l"(d) : "l"(a), "l"(b)); return d;
}
__device__ __forceinline__ float silu_f(float v) {
    return v / (1.f + __expf(-v));
}

// ---------------- int32 vs int64 edge_index detection ----------------
__global__ void detect_kernel(const void* __restrict__ ei) {
    __shared__ int ok;
    if (threadIdx.x == 0) ok = 1;
    __syncthreads();
    const long long* p = (const long long*)ei;
    long long v = p[threadIdx.x];
    if (v < 0 || v >= NN) atomicExch(&ok, 0);
    __syncthreads();
    if (threadIdx.x == 0) g_is64 = ok;
}

// ---------------- per-node layer-1 partials (f32x2) ----------------
__global__ __launch_bounds__(128)
void precompute_kernel(const float* __restrict__ h, const float* __restrict__ t_emb,
                       const float* __restrict__ We_w1, const float* __restrict__ We_b1,
                       const float* __restrict__ Wx_w1, const float* __restrict__ Wx_b1)
{
    __shared__ float hbufT[HH * PC_NB];
    __shared__ float tbufT[TDD * PC_NB];
    int col = threadIdx.x;
    int n0 = blockIdx.x * PC_NB;

    for (int i = col; i < PC_NB * HH; i += 128) {
        int j = i >> 7, k = i & 127;
        hbufT[k * PC_NB + j] = h[(size_t)(n0 + j) * HH + k];
    }
    for (int i = col; i < PC_NB * TDD; i += 128) {
        int j = i >> 5, k = i & 31;
        tbufT[k * PC_NB + j] = t_emb[(size_t)(n0 + j) * TDD + k];
    }
    __syncthreads();

    u64 a1[4], a2[4], b1[4], b2[4];
    {
        float be = We_b1[col], bx = Wx_b1[col];
        u64 pbe = pk(be, be), pbx = pk(bx, bx), z = pk(0.f, 0.f);
#pragma unroll
        for (int j = 0; j < 4; j++) { a1[j] = pbe; b1[j] = pbx; a2[j] = z; b2[j] = z; }
    }
#pragma unroll 2
    for (int k = 0; k < HH; k++) {
        float wa1 = We_w1[(size_t)k * HH + col];
        float wa2 = We_w1[(size_t)(HH + k) * HH + col];
        float wb1 = Wx_w1[(size_t)k * HH + col];
        float wb2 = Wx_w1[(size_t)(HH + k) * HH + col];
        u64 pa1 = pk(wa1, wa1), pa2 = pk(wa2, wa2);
        u64 pb1 = pk(wb1, wb1), pb2 = pk(wb2, wb2);
        const u64* ph = (const u64*)(hbufT + k * PC_NB);
#pragma unroll
        for (int j = 0; j < 4; j++) {
            u64 hv = ph[j];
            a1[j] = f2fma(hv, pa1, a1[j]);
            a2[j] = f2fma(hv, pa2, a2[j]);
            b1[j] = f2fma(hv, pb1, b1[j]);
            b2[j] = f2fma(hv, pb2, b2[j]);
        }
    }
#pragma unroll 2
    for (int k = 0; k < TDD; k++) {
        float wta = We_w1[(size_t)(273 + k) * HH + col];
        float wtb = Wx_w1[(size_t)(272 + k) * HH + col];
        u64 pta = pk(wta, wta), ptb = pk(wtb, wtb);
        const u64* pt = (const u64*)(tbufT + k * PC_NB);
#pragma unroll
        for (int j = 0; j < 4; j++) {
            u64 tv = pt[j];
            a1[j] = f2fma(tv, pta, a1[j]);
            b1[j] = f2fma(tv, ptb, b1[j]);
        }
    }
#pragma unroll
    for (int j = 0; j < 4; j++) {
        size_t o0 = (size_t)(n0 + 2 * j) * HH + col;
        size_t o1 = o0 + HH;
        float x0, x1;
        upk(x0, x1, a1[j]); g_A1[o0] = x0; g_A1[o1] = x1;
        upk(x0, x1, a2[j]); g_A2[o0] = x0; g_A2[o1] = x1;
        upk(x0, x1, b1[j]); g_B1[o0] = x0; g_B1[o1] = x1;
        upk(x0, x1, b2[j]); g_B2[o0] = x0; g_B2[o1] = x1;
        g_msg[o0] = 0.f; g_msg[o1] = 0.f;
    }
    if (col < PC_NB * 3) g_coord[n0 * 3 + col] = 0.f;
}

// ================= E1: message path (phi_e + attention + msg scatter) =================
#define E1_W2    0
#define E1_WEXT  (E1_W2 + 16384)        // 17 x 128
#define E1_WATT  (E1_WEXT + 2176)
#define E1_B2    (E1_WATT + 128)
#define E1_EXT   (E1_B2 + 128)          // 17 x 64 [row][edge]
#define E1_SRC   (E1_EXT + 17*64)
#define E1_DST   (E1_SRC + 64)
#define E1_M1T   (E1_DST + 64)          // 128 x 64 [k][edge]
#define E1_RED   (E1_M1T + 128*64)      // 8 warps x 8 u64 (=128 floats)
#define E1_ATT   (E1_RED + 128)
#define E1_SIZE  (E1_ATT + 64)
#define E1_BYTES (E1_SIZE * 4)

__global__ __launch_bounds__(256, 2)
void e1_kernel(const float* __restrict__ x, const void* __restrict__ ei,
               const float* __restrict__ edge_attr,
               const float* __restrict__ We_w1,
               const float* __restrict__ We_w2, const float* __restrict__ We_b2,
               const float* __restrict__ Watt_w, const float* __restrict__ Watt_b)
{
    extern __shared__ float sm[];
    int tid = threadIdx.x;
    int e0 = blockIdx.x * ET;
    int is64 = g_is64;

    // weights (vectorized staging)
    {
        const float4* src = (const float4*)We_w2;
        float4* dst = (float4*)(sm + E1_W2);
        for (int i = tid; i < 4096; i += 256) dst[i] = src[i];
    }
    for (int i = tid; i < 2176; i += 256) sm[E1_WEXT + i] = We_w1[256 * 128 + i];
    if (tid < 128) { sm[E1_WATT + tid] = Watt_w[tid]; sm[E1_B2 + tid] = We_b2[tid]; }

    int* sSrc = (int*)(sm + E1_SRC);
    int* sDst = (int*)(sm + E1_DST);

    if (tid < ET) {
        int ge = e0 + tid;
        int s, d;
        if (is64) { const long long* p = (const long long*)ei; s = (int)p[ge]; d = (int)p[NE + ge]; }
        else      { const int* p = (const int*)ei;             s = p[ge];      d = p[NE + ge]; }
        sSrc[tid] = s; sDst[tid] = d;
        float dx = x[s * 3 + 0] - x[d * 3 + 0];
        float dy = x[s * 3 + 1] - x[d * 3 + 1];
        float dz = x[s * 3 + 2] - x[d * 3 + 2];
        sm[E1_EXT + tid] = dx * dx + dy * dy + dz * dz;
    }
    for (int idx = tid; idx < ET * EDD; idx += 256) {
        int j = idx >> 6, e = idx & 63;
        sm[E1_EXT + (1 + j) * 64 + e] = edge_attr[(size_t)(e0 + e) * EDD + j];
    }
    __syncthreads();

    // ---- phase A: u = A1[s]+A2[d] + ext@Wext ; silu ; store transposed ----
    {
        int e = tid & 63, cg = tid >> 6;   // 32 cols per thread
        int s = sSrc[e], d = sDst[e];
        const ulonglong2* a1p = (const ulonglong2*)(g_A1 + (size_t)s * HH + cg * 32);
        const ulonglong2* a2p = (const ulonglong2*)(g_A2 + (size_t)d * HH + cg * 32);
        u64 u[16];
#pragma unroll
        for (int i = 0; i < 8; i++) {
            ulonglong2 va = a1p[i], vb = a2p[i];
            u[2 * i]     = f2add(va.x, vb.x);
            u[2 * i + 1] = f2add(va.y, vb.y);
        }
#pragma unroll 1
        for (int r = 0; r < 17; r++) {
            float ev = sm[E1_EXT + r * 64 + e];
            u64 ev2 = pk(ev, ev);
            const ulonglong2* wp = (const ulonglong2*)(sm + E1_WEXT + r * 128 + cg * 32);
#pragma unroll
            for (int i = 0; i < 8; i++) {
                ulonglong2 w = wp[i];
                u[2 * i]     = f2fma(ev2, w.x, u[2 * i]);
                u[2 * i + 1] = f2fma(ev2, w.y, u[2 * i + 1]);
            }
        }
#pragma unroll
        for (int i = 0; i < 16; i++) {
            float a, b; upk(a, b, u[i]);
            sm[E1_M1T + (cg * 32 + 2 * i) * 64 + e]     = silu_f(a);
            sm[E1_M1T + (cg * 32 + 2 * i + 1) * 64 + e] = silu_f(b);
        }
    }
    __syncthreads();

    // ---- GEMM: m2 = m1 @ We_w2 + b2 ; thread = (c 0..63, eg 0..3), TE=16, TC=2 ----
    int c = tid & 63, eg = tid >> 6;
    u64 acc0[8], acc1[8];
    {
        float b0 = sm[E1_B2 + c], b1 = sm[E1_B2 + c + 64];
        u64 p0 = pk(b0, b0), p1 = pk(b1, b1);
#pragma unroll
        for (int q = 0; q < 8; q++) { acc0[q] = p0; acc1[q] = p1; }
    }
#pragma unroll 4
    for (int k = 0; k < 128; k++) {
        float w0 = sm[E1_W2 + k * 128 + c];
        float w1 = sm[E1_W2 + k * 128 + c + 64];
        u64 ww0 = pk(w0, w0), ww1 = pk(w1, w1);
        const ulonglong2* mp = (const ulonglong2*)(sm + E1_M1T + k * 64 + eg * 16);
        ulonglong2 m0 = mp[0], m1 = mp[1], m2 = mp[2], m3 = mp[3];
        acc0[0] = f2fma(m0.x, ww0, acc0[0]); acc1[0] = f2fma(m0.x, ww1, acc1[0]);
        acc0[1] = f2fma(m0.y, ww0, acc0[1]); acc1[1] = f2fma(m0.y, ww1, acc1[1]);
        acc0[2] = f2fma(m1.x, ww0, acc0[2]); acc1[2] = f2fma(m1.x, ww1, acc1[2]);
        acc0[3] = f2fma(m1.y, ww0, acc0[3]); acc1[3] = f2fma(m1.y, ww1, acc1[3]);
        acc0[4] = f2fma(m2.x, ww0, acc0[4]); acc1[4] = f2fma(m2.x, ww1, acc1[4]);
        acc0[5] = f2fma(m2.y, ww0, acc0[5]); acc1[5] = f2fma(m2.y, ww1, acc1[5]);
        acc0[6] = f2fma(m3.x, ww0, acc0[6]); acc1[6] = f2fma(m3.x, ww1, acc1[6]);
        acc0[7] = f2fma(m3.y, ww0, acc0[7]); acc1[7] = f2fma(m3.y, ww1, acc1[7]);
    }

    // attention partial
    {
        float wa0 = sm[E1_WATT + c], wa1 = sm[E1_WATT + c + 64];
        u64 pwa0 = pk(wa0, wa0), pwa1 = pk(wa1, wa1), z = pk(0.f, 0.f);
        u64 pa[8];
#pragma unroll
        for (int q = 0; q < 8; q++)
            pa[q] = f2fma(acc0[q], pwa0, f2fma(acc1[q], pwa1, z));
#pragma unroll
        for (int msk = 16; msk > 0; msk >>= 1)
#pragma unroll
            for (int q = 0; q < 8; q++)
                pa[q] = f2add(pa[q], __shfl_xor_sync(0xffffffffu, pa[q], msk));
        if ((tid & 31) == 0) {
            int warp = tid >> 5;
            u64* red = (u64*)(sm + E1_RED);
#pragma unroll
            for (int q = 0; q < 8; q++) red[warp * 8 + q] = pa[q];
        }
    }
    __syncthreads();

    if (tid < ET) {
        int e = tid, eg2 = e >> 4, q16 = e & 15;
        float s = sm[E1_RED + (2 * eg2) * 16 + q16] + sm[E1_RED + (2 * eg2 + 1) * 16 + q16];
        sm[E1_ATT + e] = 1.f / (1.f + __expf(-(s + Watt_b[0])));
    }
    __syncthreads();

    // msg scatter (NE % ET == 0 -> no guards)
#pragma unroll
    for (int q = 0; q < 8; q++) {
        int e = eg * 16 + 2 * q;
        float att0 = sm[E1_ATT + e], att1 = sm[E1_ATT + e + 1];
        int d0 = sDst[e], d1 = sDst[e + 1];
        float a, b;
        upk(a, b, acc0[q]);
        atomicAdd(&g_msg[(size_t)d0 * HH + c], att0 * a);
        atomicAdd(&g_msg[(size_t)d1 * HH + c], att1 * b);
        upk(a, b, acc1[q]);
        atomicAdd(&g_msg[(size_t)d0 * HH + c + 64], att0 * a);
        atomicAdd(&g_msg[(size_t)d1 * HH + c + 64], att1 * b);
    }
}

// ================= E2: coord path (phi_x + coord scatter) =================
#define E2_W2    0
#define E2_WEXT  (E2_W2 + 16384)        // 16 x 128
#define E2_WX3   (E2_WEXT + 2048)
#define E2_B2    (E2_WX3 + 128)
#define E2_EXT   (E2_B2 + 128)          // 16 x 64
#define E2_DIFFN (E2_EXT + 16*64)       // 3 x 64
#define E2_SRC   (E2_DIFFN + 192)
#define E2_DST   (E2_SRC + 64)
#define E2_C1T   (E2_DST + 64)          // 128 x 64
#define E2_RED   (E2_C1T + 128*64)      // 8 x 8 u64
#define E2_SIZE  (E2_RED + 128)
#define E2_BYTES (E2_SIZE * 4)

__global__ __launch_bounds__(256, 2)
void e2_kernel(const float* __restrict__ x, const void* __restrict__ ei,
               const float* __restrict__ edge_attr,
               const float* __restrict__ Wx_w1,
               const float* __restrict__ Wx_w2, const float* __restrict__ Wx_b2,
               const float* __restrict__ Wx_w3)
{
    extern __shared__ float sm[];
    int tid = threadIdx.x;
    int e0 = blockIdx.x * ET;
    int is64 = g_is64;

    {
        const float4* src = (const float4*)Wx_w2;
        float4* dst = (float4*)(sm + E2_W2);
        for (int i = tid; i < 4096; i += 256) dst[i] = src[i];
    }
    for (int i = tid; i < 2048; i += 256) sm[E2_WEXT + i] = Wx_w1[256 * 128 + i];
    if (tid < 128) { sm[E2_WX3 + tid] = Wx_w3[tid]; sm[E2_B2 + tid] = Wx_b2[tid]; }

    int* sSrc = (int*)(sm + E2_SRC);
    int* sDst = (int*)(sm + E2_DST);

    if (tid < ET) {
        int ge = e0 + tid;
        int s, d;
        if (is64) { const long long* p = (const long long*)ei; s = (int)p[ge]; d = (int)p[NE + ge]; }
        else      { const int* p = (const int*)ei;             s = p[ge];      d = p[NE + ge]; }
        sSrc[tid] = s; sDst[tid] = d;
        float dx = x[s * 3 + 0] - x[d * 3 + 0];
        float dy = x[s * 3 + 1] - x[d * 3 + 1];
        float dz = x[s * 3 + 2] - x[d * 3 + 2];
        float dsq = dx * dx + dy * dy + dz * dz;
        float inv = 1.f / (sqrtf(dsq + 1e-8f) + 1.f);
        sm[E2_DIFFN + 0 * 64 + tid] = dx * inv;
        sm[E2_DIFFN + 1 * 64 + tid] = dy * inv;
        sm[E2_DIFFN + 2 * 64 + tid] = dz * inv;
    }
    for (int idx = tid; idx < ET * EDD; idx += 256) {
        int j = idx >> 6, e = idx & 63;
        sm[E2_EXT + j * 64 + e] = edge_attr[(size_t)(e0 + e) * EDD + j];
    }
    __syncthreads();

    // phase A
    {
        int e = tid & 63, cg = tid >> 6;
        int s = sSrc[e], d = sDst[e];
        const ulonglong2* b1p = (const ulonglong2*)(g_B1 + (size_t)s * HH + cg * 32);
        const ulonglong2* b2p = (const ulonglong2*)(g_B2 + (size_t)d * HH + cg * 32);
        u64 u[16];
#pragma unroll
        for (int i = 0; i < 8; i++) {
            ulonglong2 va = b1p[i], vb = b2p[i];
            u[2 * i]     = f2add(va.x, vb.x);
            u[2 * i + 1] = f2add(va.y, vb.y);
        }
#pragma unroll 1
        for (int r = 0; r < 16; r++) {
            float ev = sm[E2_EXT + r * 64 + e];
            u64 ev2 = pk(ev, ev);
            const ulonglong2* wp = (const ulonglong2*)(sm + E2_WEXT + r * 128 + cg * 32);
#pragma unroll
            for (int i = 0; i < 8; i++) {
                ulonglong2 w = wp[i];
                u[2 * i]     = f2fma(ev2, w.x, u[2 * i]);
                u[2 * i + 1] = f2fma(ev2, w.y, u[2 * i + 1]);
            }
        }
#pragma unroll
        for (int i = 0; i < 16; i++) {
            float a, b; upk(a, b, u[i]);
            sm[E2_C1T + (cg * 32 + 2 * i) * 64 + e]     = silu_f(a);
            sm[E2_C1T + (cg * 32 + 2 * i + 1) * 64 + e] = silu_f(b);
        }
    }
    __syncthreads();

    // GEMM: c2 = c1 @ Wx_w2 + b
    int c = tid & 63, eg = tid >> 6;
    u64 acc0[8], acc1[8];
    {
        float b0 = sm[E2_B2 + c], b1 = sm[E2_B2 + c + 64];
        u64 p0 = pk(b0, b0), p1 = pk(b1, b1);
#pragma unroll
        for (int q = 0; q < 8; q++) { acc0[q] = p0; acc1[q] = p1; }
    }
#pragma unroll 4
    for (int k = 0; k < 128; k++) {
        float w0 = sm[E2_W2 + k * 128 + c];
        float w1 = sm[E2_W2 + k * 128 + c + 64];
        u64 ww0 = pk(w0, w0), ww1 = pk(w1, w1);
        const ulonglong2* mp = (const ulonglong2*)(sm + E2_C1T + k * 64 + eg * 16);
        ulonglong2 m0 = mp[0], m1 = mp[1], m2 = mp[2], m3 = mp[3];
        acc0[0] = f2fma(m0.x, ww0, acc0[0]); acc1[0] = f2fma(m0.x, ww1, acc1[0]);
        acc0[1] = f2fma(m0.y, ww0, acc0[1]); acc1[1] = f2fma(m0.y, ww1, acc1[1]);
        acc0[2] = f2fma(m1.x, ww0, acc0[2]); acc1[2] = f2fma(m1.x, ww1, acc1[2]);
        acc0[3] = f2fma(m1.y, ww0, acc0[3]); acc1[3] = f2fma(m1.y, ww1, acc1[3]);
        acc0[4] = f2fma(m2.x, ww0, acc0[4]); acc1[4] = f2fma(m2.x, ww1, acc1[4]);
        acc0[5] = f2fma(m2.y, ww0, acc0[5]); acc1[5] = f2fma(m2.y, ww1, acc1[5]);
        acc0[6] = f2fma(m3.x, ww0, acc0[6]); acc1[6] = f2fma(m3.x, ww1, acc1[6]);
        acc0[7] = f2fma(m3.y, ww0, acc0[7]); acc1[7] = f2fma(m3.y, ww1, acc1[7]);
    }

    // coord-weight partial
    {
        float w30 = sm[E2_WX3 + c], w31 = sm[E2_WX3 + c + 64];
        u64 pc[8];
#pragma unroll
        for (int q = 0; q < 8; q++) {
            float a, b, p0, p1;
            upk(a, b, acc0[q]);
            p0 = silu_f(a) * w30; p1 = silu_f(b) * w30;
            upk(a, b, acc1[q]);
            p0 += silu_f(a) * w31; p1 += silu_f(b) * w31;
            pc[q] = pk(p0, p1);
        }
#pragma unroll
        for (int msk = 16; msk > 0; msk >>= 1)
#pragma unroll
            for (int q = 0; q < 8; q++)
                pc[q] = f2add(pc[q], __shfl_xor_sync(0xffffffffu, pc[q], msk));
        if ((tid & 31) == 0) {
            int warp = tid >> 5;
            u64* red = (u64*)(sm + E2_RED);
#pragma unroll
            for (int q = 0; q < 8; q++) red[warp * 8 + q] = pc[q];
        }
    }
    __syncthreads();

    if (tid < ET) {
        int e = tid, eg2 = e >> 4, q16 = e & 15;
        float s = sm[E2_RED + (2 * eg2) * 16 + q16] + sm[E2_RED + (2 * eg2 + 1) * 16 + q16];
        float cw = tanhf(s) * 2.5f;
        int d = sDst[e];
        atomicAdd(&g_coord[d * 3 + 0], sm[E2_DIFFN + 0 * 64 + e] * cw);
        atomicAdd(&g_coord[d * 3 + 1], sm[E2_DIFFN + 1 * 64 + e] * cw);
        atomicAdd(&g_coord[d * 3 + 2], sm[E2_DIFFN + 2 * 64 + e] * cw);
    }
}

// ---------------- phi_h + output assembly ----------------
#define NODE_SMEM_FLOATS (256*128 + 128*128 + 128 + 128 + 256*PH_PAD + 128*PH_PAD)
#define NODE_SMEM_BYTES  (NODE_SMEM_FLOATS * 4)

__global__ __launch_bounds__(512, 1)
void node_out_kernel(const float* __restrict__ h, const float* __restrict__ x,
                     const float* __restrict__ Wh_w1, const float* __restrict__ Wh_b1,
                     const float* __restrict__ Wh_w2, const float* __restrict__ Wh_b2,
                     float* __restrict__ out)
{
    extern __shared__ float sm[];
    float* sW1   = sm;
    float* sW2   = sW1 + 256 * 128;
    float* sB1   = sW2 + 128 * 128;
    float* sB2   = sB1 + 128;
    float* sInT  = sB2 + 128;
    float* sHidT = sInT + 256 * PH_PAD;

    int tid = threadIdx.x;
    {
        const float4* s1 = (const float4*)Wh_w1;
        float4* d1 = (float4*)sW1;
        for (int i = tid; i < 8192; i += 512) d1[i] = s1[i];
        const float4* s2 = (const float4*)Wh_w2;
        float4* d2 = (float4*)sW2;
        for (int i = tid; i < 4096; i += 512) d2[i] = s2[i];
    }
    if (tid < 128) { sB1[tid] = Wh_b1[tid]; sB2[tid] = Wh_b2[tid]; }

    int col = tid & 127, grp = tid >> 7;
    int jb = grp * 4;

    for (int tile = blockIdx.x; tile < NN / PH_NB; tile += gridDim.x) {
        int n0 = tile * PH_NB;
        __syncthreads();
        for (int i = tid; i < PH_NB * HH; i += 512) {
            int j = i >> 7, k = i & 127;
            int n = n0 + j;
            sInT[k * PH_PAD + j]        = h[(size_t)n * HH + k];
            sInT[(HH + k) * PH_PAD + j] = g_msg[(size_t)n * HH + k];
        }
        __syncthreads();

        u64 acc[2];
        {
            float b = sB1[col]; u64 bb = pk(b, b);
            acc[0] = bb; acc[1] = bb;
        }
#pragma unroll 4
        for (int k = 0; k < 256; k++) {
            float w = sW1[k * 128 + col];
            u64 ww = pk(w, w);
            const u64* p = (const u64*)(sInT + k * PH_PAD + jb);
            acc[0] = f2fma(p[0], ww, acc[0]);
            acc[1] = f2fma(p[1], ww, acc[1]);
        }
        {
            float a, b;
            upk(a, b, acc[0]);
            sHidT[col * PH_PAD + jb + 0] = silu_f(a);
            sHidT[col * PH_PAD + jb + 1] = silu_f(b);
            upk(a, b, acc[1]);
            sHidT[col * PH_PAD + jb + 2] = silu_f(a);
            sHidT[col * PH_PAD + jb + 3] = silu_f(b);
        }
        __syncthreads();

        u64 acc2[2];
        {
            float b = sB2[col]; u64 bb = pk(b, b);
            acc2[0] = bb; acc2[1] = bb;
        }
#pragma unroll 4
        for (int k = 0; k < 128; k++) {
            float w = sW2[k * 128 + col];
            u64 ww = pk(w, w);
            const u64* p = (const u64*)(sHidT + k * PH_PAD + jb);
            acc2[0] = f2fma(p[0], ww, acc2[0]);
            acc2[1] = f2fma(p[1], ww, acc2[1]);
        }
        {
            float a, b;
            upk(a, b, acc2[0]);
            out[(size_t)(n0 + jb + 0) * HH + col] = h[(size_t)(n0 + jb + 0) * HH + col] + a;
            out[(size_t)(n0 + jb + 1) * HH + col] = h[(size_t)(n0 + jb + 1) * HH + col] + b;
            upk(a, b, acc2[1]);
            out[(size_t)(n0 + jb + 2) * HH + col] = h[(size_t)(n0 + jb + 2) * HH + col] + a;
            out[(size_t)(n0 + jb + 3) * HH + col] = h[(size_t)(n0 + jb + 3) * HH + col] + b;
        }
        if (tid < PH_NB * 3) {
            int n = n0 + tid / 3, c = tid % 3;
            out[(size_t)NN * HH + n * 3 + c] = x[n * 3 + c] + g_coord[n * 3 + c];
        }
    }
}

// ---------------- launch ----------------
extern "C" void kernel_launch(void* const* d_in, const int* in_sizes, int n_in,
                              void* d_out, int out_size) {
    const float* h         = (const float*)d_in[0];
    const float* x         = (const float*)d_in[1];
    const void*  ei        = d_in[2];
    const float* edge_attr = (const float*)d_in[3];
    const float* t_emb     = (const float*)d_in[4];
    const float* We_w1     = (const float*)d_in[5];
    const float* We_b1     = (const float*)d_in[6];
    const float* We_w2     = (const float*)d_in[7];
    const float* We_b2     = (const float*)d_in[8];
    const float* Watt_w    = (const float*)d_in[9];
    const float* Watt_b    = (const float*)d_in[10];
    const float* Wx_w1     = (const float*)d_in[11];
    const float* Wx_b1     = (const float*)d_in[12];
    const float* Wx_w2     = (const float*)d_in[13];
    const float* Wx_b2     = (const float*)d_in[14];
    const float* Wx_w3     = (const float*)d_in[15];
    const float* Wh_w1     = (const float*)d_in[16];
    const float* Wh_b1     = (const float*)d_in[17];
    const float* Wh_w2     = (const float*)d_in[18];
    const float* Wh_b2     = (const float*)d_in[19];
    float* out = (float*)d_out;

    int nsm = 148;
    cudaDeviceGetAttribute(&nsm, cudaDevAttrMultiProcessorCount, 0);

    cudaFuncSetAttribute(e1_kernel, cudaFuncAttributeMaxDynamicSharedMemorySize, E1_BYTES);
    cudaFuncSetAttribute(e2_kernel, cudaFuncAttributeMaxDynamicSharedMemorySize, E2_BYTES);
    cudaFuncSetAttribute(node_out_kernel, cudaFuncAttributeMaxDynamicSharedMemorySize, NODE_SMEM_BYTES);

    int eblocks = NE / ET;

    detect_kernel<<<1, 256>>>(ei);
    precompute_kernel<<<NN / PC_NB, 128>>>(h, t_emb, We_w1, We_b1, Wx_w1, Wx_b1);
    e1_kernel<<<eblocks, 256, E1_BYTES>>>(x, ei, edge_attr, We_w1, We_w2, We_b2, Watt_w, Watt_b);
    e2_kernel<<<eblocks, 256, E2_BYTES>>>(x, ei, edge_attr, Wx_w1, Wx_w2, Wx_b2, Wx_w3);
    node_out_kernel<<<nsm, 512, NODE_SMEM_BYTES>>>(h, x, Wh_w1, Wh_b1, Wh_w2, Wh_b2, out);
}

// round 6
// speedup vs baseline: 1.1583x; 1.1583x over previous
#include <cuda_runtime.h>
#include <math.h>

#define NN 50000
#define NE 600000
#define HH 128
#define EDD 16
#define TDD 32

#define ET 64      // edges per block (E1/E2)
#define PC_NB 8
#define PH_NB 16
#define PH_PAD 20

static_assert(NN % PC_NB == 0, "precompute exact");
static_assert(NN % PH_NB == 0, "node tile exact");
static_assert(NE % ET == 0, "edge tile exact");

// ---------------- device scratch ----------------
__device__ float g_A1[NN * HH];
__device__ float g_A2[NN * HH];
__device__ float g_B1[NN * HH];
__device__ float g_B2[NN * HH];
__device__ float g_msg[NN * HH];
__device__ float g_coord[NN * 3];
__device__ int   g_is64;

typedef unsigned long long u64;

__device__ __forceinline__ u64 pk(float lo, float hi) {
    u64 r; asm("mov.b64 %0,{%1,%2};" : "=l"(r) : "f"(lo), "f"(hi)); return r;
}
__device__ __forceinline__ void upk(float& lo, float& hi, u64 v) {
    asm("mov.b64 {%0,%1},%2;" : "=f"(lo), "=f"(hi) : "l"(v));
}
__device__ __forceinline__ u64 f2fma(u64 a, u64 b, u64 c) {
    u64 d; asm("fma.rn.f32x2 %0,%1,%2,%3;" : "=l"(d) : "l"(a), "l"(b), "l"(c)); return d;
}
__device__ __forceinline__ u64 f2add(u64 a, u64 b) {
    u64 d; asm("add.rn.f32x2 %0,%1,%2;" : "=l"(d) : "l"(a), "l"(b)); return d;
}
__device__ __forceinline__ void red2(float* addr, float a, float b) {
    asm volatile("red.global.add.v2.f32 [%0], {%1,%2};" :: "l"(addr), "f"(a), "f"(b) : "memory");
}
__device__ __forceinline__ float silu_f(float v) {
    return v / (1.f + __expf(-v));
}

// ---------------- int32 vs int64 edge_index detection ----------------
__global__ void detect_kernel(const void* __restrict__ ei) {
    __shared__ int ok;
    if (threadIdx.x == 0) ok = 1;
    __syncthreads();
    const long long* p = (const long long*)ei;
    long long v = p[threadIdx.x];
    if (v < 0 || v >= NN) atomicExch(&ok, 0);
    __syncthreads();
    if (threadIdx.x == 0) g_is64 = ok;
}

// ---------------- per-node layer-1 partials (f32x2) ----------------
__global__ __launch_bounds__(128)
void precompute_kernel(const float* __restrict__ h, const float* __restrict__ t_emb,
                       const float* __restrict__ We_w1, const float* __restrict__ We_b1,
                       const float* __restrict__ Wx_w1, const float* __restrict__ Wx_b1)
{
    __shared__ float hbufT[HH * PC_NB];
    __shared__ float tbufT[TDD * PC_NB];
    int col = threadIdx.x;
    int n0 = blockIdx.x * PC_NB;

    for (int i = col; i < PC_NB * HH; i += 128) {
        int j = i >> 7, k = i & 127;
        hbufT[k * PC_NB + j] = h[(size_t)(n0 + j) * HH + k];
    }
    for (int i = col; i < PC_NB * TDD; i += 128) {
        int j = i >> 5, k = i & 31;
        tbufT[k * PC_NB + j] = t_emb[(size_t)(n0 + j) * TDD + k];
    }
    __syncthreads();

    u64 a1[4], a2[4], b1[4], b2[4];
    {
        float be = We_b1[col], bx = Wx_b1[col];
        u64 pbe = pk(be, be), pbx = pk(bx, bx), z = pk(0.f, 0.f);
#pragma unroll
        for (int j = 0; j < 4; j++) { a1[j] = pbe; b1[j] = pbx; a2[j] = z; b2[j] = z; }
    }
#pragma unroll 2
    for (int k = 0; k < HH; k++) {
        float wa1 = We_w1[(size_t)k * HH + col];
        float wa2 = We_w1[(size_t)(HH + k) * HH + col];
        float wb1 = Wx_w1[(size_t)k * HH + col];
        float wb2 = Wx_w1[(size_t)(HH + k) * HH + col];
        u64 pa1 = pk(wa1, wa1), pa2 = pk(wa2, wa2);
        u64 pb1 = pk(wb1, wb1), pb2 = pk(wb2, wb2);
        const u64* ph = (const u64*)(hbufT + k * PC_NB);
#pragma unroll
        for (int j = 0; j < 4; j++) {
            u64 hv = ph[j];
            a1[j] = f2fma(hv, pa1, a1[j]);
            a2[j] = f2fma(hv, pa2, a2[j]);
            b1[j] = f2fma(hv, pb1, b1[j]);
            b2[j] = f2fma(hv, pb2, b2[j]);
        }
    }
#pragma unroll 2
    for (int k = 0; k < TDD; k++) {
        float wta = We_w1[(size_t)(273 + k) * HH + col];
        float wtb = Wx_w1[(size_t)(272 + k) * HH + col];
        u64 pta = pk(wta, wta), ptb = pk(wtb, wtb);
        const u64* pt = (const u64*)(tbufT + k * PC_NB);
#pragma unroll
        for (int j = 0; j < 4; j++) {
            u64 tv = pt[j];
            a1[j] = f2fma(tv, pta, a1[j]);
            b1[j] = f2fma(tv, ptb, b1[j]);
        }
    }
#pragma unroll
    for (int j = 0; j < 4; j++) {
        size_t o0 = (size_t)(n0 + 2 * j) * HH + col;
        size_t o1 = o0 + HH;
        float x0, x1;
        upk(x0, x1, a1[j]); g_A1[o0] = x0; g_A1[o1] = x1;
        upk(x0, x1, a2[j]); g_A2[o0] = x0; g_A2[o1] = x1;
        upk(x0, x1, b1[j]); g_B1[o0] = x0; g_B1[o1] = x1;
        upk(x0, x1, b2[j]); g_B2[o0] = x0; g_B2[o1] = x1;
        g_msg[o0] = 0.f; g_msg[o1] = 0.f;
    }
    if (col < PC_NB * 3) g_coord[n0 * 3 + col] = 0.f;
}

// ================= E1: message path (phi_e + attention + msg scatter) =================
// smem: no W2 (read from L1); 47KB -> 3 blocks/SM
#define E1_WEXT  0                  // 17 x 128
#define E1_WATT  (E1_WEXT + 2176)
#define E1_B2    (E1_WATT + 128)
#define E1_EXT   (E1_B2 + 128)      // 17 x 64 [row][edge]
#define E1_SRC   (E1_EXT + 17*64)
#define E1_DST   (E1_SRC + 64)
#define E1_M1T   (E1_DST + 64)      // 128 x 64 [k][edge]
#define E1_RED   (E1_M1T + 128*64)  // 8 warps x 8 u64
#define E1_ATT   (E1_RED + 128)
#define E1_SIZE  (E1_ATT + 64)
#define E1_BYTES (E1_SIZE * 4)

__global__ __launch_bounds__(256, 3)
void e1_kernel(const float* __restrict__ x, const void* __restrict__ ei,
               const float* __restrict__ edge_attr,
               const float* __restrict__ We_w1,
               const float* __restrict__ We_w2, const float* __restrict__ We_b2,
               const float* __restrict__ Watt_w, const float* __restrict__ Watt_b)
{
    extern __shared__ float sm[];
    int tid = threadIdx.x;
    int e0 = blockIdx.x * ET;
    int is64 = g_is64;
    float attb = Watt_b[0];

    for (int i = tid; i < 2176; i += 256) sm[E1_WEXT + i] = We_w1[256 * 128 + i];
    if (tid < 128) { sm[E1_WATT + tid] = Watt_w[tid]; sm[E1_B2 + tid] = We_b2[tid]; }

    int* sSrc = (int*)(sm + E1_SRC);
    int* sDst = (int*)(sm + E1_DST);

    if (tid < ET) {
        int ge = e0 + tid;
        int s, d;
        if (is64) { const long long* p = (const long long*)ei; s = (int)p[ge]; d = (int)p[NE + ge]; }
        else      { const int* p = (const int*)ei;             s = p[ge];      d = p[NE + ge]; }
        sSrc[tid] = s; sDst[tid] = d;
        float dx = x[s * 3 + 0] - x[d * 3 + 0];
        float dy = x[s * 3 + 1] - x[d * 3 + 1];
        float dz = x[s * 3 + 2] - x[d * 3 + 2];
        sm[E1_EXT + tid] = dx * dx + dy * dy + dz * dz;
    }
    for (int idx = tid; idx < ET * EDD; idx += 256) {
        int j = idx >> 6, e = idx & 63;
        sm[E1_EXT + (1 + j) * 64 + e] = edge_attr[(size_t)(e0 + e) * EDD + j];
    }
    __syncthreads();

    // ---- phase A: u = A1[s]+A2[d] + ext@Wext ; silu ; store transposed ----
    {
        int e = tid & 63, cg = tid >> 6;   // 32 cols per thread
        int s = sSrc[e], d = sDst[e];
        const ulonglong2* a1p = (const ulonglong2*)(g_A1 + (size_t)s * HH + cg * 32);
        const ulonglong2* a2p = (const ulonglong2*)(g_A2 + (size_t)d * HH + cg * 32);
        u64 u[16];
#pragma unroll
        for (int i = 0; i < 8; i++) {
            ulonglong2 va = a1p[i], vb = a2p[i];
            u[2 * i]     = f2add(va.x, vb.x);
            u[2 * i + 1] = f2add(va.y, vb.y);
        }
#pragma unroll 1
        for (int r = 0; r < 17; r++) {
            float ev = sm[E1_EXT + r * 64 + e];
            u64 ev2 = pk(ev, ev);
            const ulonglong2* wp = (const ulonglong2*)(sm + E1_WEXT + r * 128 + cg * 32);
#pragma unroll
            for (int i = 0; i < 8; i++) {
                ulonglong2 w = wp[i];
                u[2 * i]     = f2fma(ev2, w.x, u[2 * i]);
                u[2 * i + 1] = f2fma(ev2, w.y, u[2 * i + 1]);
            }
        }
#pragma unroll
        for (int i = 0; i < 16; i++) {
            float a, b; upk(a, b, u[i]);
            sm[E1_M1T + (cg * 32 + 2 * i) * 64 + e]     = silu_f(a);
            sm[E1_M1T + (cg * 32 + 2 * i + 1) * 64 + e] = silu_f(b);
        }
    }
    __syncthreads();

    // ---- GEMM: thread = (cidx 0..63 -> cols 2c,2c+1 ; eg 0..3 -> 16 edges) ----
    int cidx = tid & 63, eg = tid >> 6;
    int c0 = 2 * cidx;
    u64 acc0[8], acc1[8];
    {
        float2 bb = *(const float2*)(sm + E1_B2 + c0);
        u64 p0 = pk(bb.x, bb.x), p1 = pk(bb.y, bb.y);
#pragma unroll
        for (int q = 0; q < 8; q++) { acc0[q] = p0; acc1[q] = p1; }
    }
#pragma unroll 4
    for (int k = 0; k < 128; k++) {
        float2 w = __ldg((const float2*)(We_w2 + k * 128 + c0));
        u64 ww0 = pk(w.x, w.x), ww1 = pk(w.y, w.y);
        const ulonglong2* mp = (const ulonglong2*)(sm + E1_M1T + k * 64 + eg * 16);
        ulonglong2 m0 = mp[0], m1 = mp[1], m2 = mp[2], m3 = mp[3];
        acc0[0] = f2fma(m0.x, ww0, acc0[0]); acc1[0] = f2fma(m0.x, ww1, acc1[0]);
        acc0[1] = f2fma(m0.y, ww0, acc0[1]); acc1[1] = f2fma(m0.y, ww1, acc1[1]);
        acc0[2] = f2fma(m1.x, ww0, acc0[2]); acc1[2] = f2fma(m1.x, ww1, acc1[2]);
        acc0[3] = f2fma(m1.y, ww0, acc0[3]); acc1[3] = f2fma(m1.y, ww1, acc1[3]);
        acc0[4] = f2fma(m2.x, ww0, acc0[4]); acc1[4] = f2fma(m2.x, ww1, acc1[4]);
        acc0[5] = f2fma(m2.y, ww0, acc0[5]); acc1[5] = f2fma(m2.y, ww1, acc1[5]);
        acc0[6] = f2fma(m3.x, ww0, acc0[6]); acc1[6] = f2fma(m3.x, ww1, acc1[6]);
        acc0[7] = f2fma(m3.y, ww0, acc0[7]); acc1[7] = f2fma(m3.y, ww1, acc1[7]);
    }

    // attention partial
    {
        float2 wa = *(const float2*)(sm + E1_WATT + c0);
        u64 pwa0 = pk(wa.x, wa.x), pwa1 = pk(wa.y, wa.y), z = pk(0.f, 0.f);
        u64 pa[8];
#pragma unroll
        for (int q = 0; q < 8; q++)
            pa[q] = f2fma(acc0[q], pwa0, f2fma(acc1[q], pwa1, z));
#pragma unroll
        for (int msk = 16; msk > 0; msk >>= 1)
#pragma unroll
            for (int q = 0; q < 8; q++)
                pa[q] = f2add(pa[q], __shfl_xor_sync(0xffffffffu, pa[q], msk));
        if ((tid & 31) == 0) {
            int warp = tid >> 5;
            u64* red = (u64*)(sm + E1_RED);
#pragma unroll
            for (int q = 0; q < 8; q++) red[warp * 8 + q] = pa[q];
        }
    }
    __syncthreads();

    if (tid < ET) {
        int e = tid, eg2 = e >> 4, q16 = e & 15;
        float s = sm[E1_RED + (2 * eg2) * 16 + q16] + sm[E1_RED + (2 * eg2 + 1) * 16 + q16];
        sm[E1_ATT + e] = 1.f / (1.f + __expf(-(s + attb)));
    }
    __syncthreads();

    // msg scatter: vectorized red.v2 (cols c0, c0+1 contiguous, 8B aligned)
#pragma unroll
    for (int q = 0; q < 8; q++) {
        int e = eg * 16 + 2 * q;
        float att0 = sm[E1_ATT + e], att1 = sm[E1_ATT + e + 1];
        int d0 = sDst[e], d1 = sDst[e + 1];
        float a0, b0, a1, b1;
        upk(a0, b0, acc0[q]);   // col c0: edge e, edge e+1
        upk(a1, b1, acc1[q]);   // col c0+1
        red2(&g_msg[(size_t)d0 * HH + c0], att0 * a0, att0 * a1);
        red2(&g_msg[(size_t)d1 * HH + c0], att1 * b0, att1 * b1);
    }
}

// ================= E2: coord path (phi_x + coord scatter) =================
#define E2_WEXT  0                  // 16 x 128
#define E2_WX3   (E2_WEXT + 2048)
#define E2_B2    (E2_WX3 + 128)
#define E2_EXT   (E2_B2 + 128)      // 16 x 64
#define E2_DIFFN (E2_EXT + 16*64)   // 3 x 64
#define E2_SRC   (E2_DIFFN + 192)
#define E2_DST   (E2_SRC + 64)
#define E2_C1T   (E2_DST + 64)      // 128 x 64
#define E2_RED   (E2_C1T + 128*64)  // 8 x 8 u64
#define E2_SIZE  (E2_RED + 128)
#define E2_BYTES (E2_SIZE * 4)

__global__ __launch_bounds__(256, 3)
void e2_kernel(const float* __restrict__ x, const void* __restrict__ ei,
               const float* __restrict__ edge_attr,
               const float* __restrict__ Wx_w1,
               const float* __restrict__ Wx_w2, const float* __restrict__ Wx_b2,
               const float* __restrict__ Wx_w3)
{
    extern __shared__ float sm[];
    int tid = threadIdx.x;
    int e0 = blockIdx.x * ET;
    int is64 = g_is64;

    for (int i = tid; i < 2048; i += 256) sm[E2_WEXT + i] = Wx_w1[256 * 128 + i];
    if (tid < 128) { sm[E2_WX3 + tid] = Wx_w3[tid]; sm[E2_B2 + tid] = Wx_b2[tid]; }

    int* sSrc = (int*)(sm + E2_SRC);
    int* sDst = (int*)(sm + E2_DST);

    if (tid < ET) {
        int ge = e0 + tid;
        int s, d;
        if (is64) { const long long* p = (const long long*)ei; s = (int)p[ge]; d = (int)p[NE + ge]; }
        else      { const int* p = (const int*)ei;             s = p[ge];      d = p[NE + ge]; }
        sSrc[tid] = s; sDst[tid] = d;
        float dx = x[s * 3 + 0] - x[d * 3 + 0];
        float dy = x[s * 3 + 1] - x[d * 3 + 1];
        float dz = x[s * 3 + 2] - x[d * 3 + 2];
        float dsq = dx * dx + dy * dy + dz * dz;
        float inv = 1.f / (sqrtf(dsq + 1e-8f) + 1.f);
        sm[E2_DIFFN + 0 * 64 + tid] = dx * inv;
        sm[E2_DIFFN + 1 * 64 + tid] = dy * inv;
        sm[E2_DIFFN + 2 * 64 + tid] = dz * inv;
    }
    for (int idx = tid; idx < ET * EDD; idx += 256) {
        int j = idx >> 6, e = idx & 63;
        sm[E2_EXT + j * 64 + e] = edge_attr[(size_t)(e0 + e) * EDD + j];
    }
    __syncthreads();

    // phase A
    {
        int e = tid & 63, cg = tid >> 6;
        int s = sSrc[e], d = sDst[e];
        const ulonglong2* b1p = (const ulonglong2*)(g_B1 + (size_t)s * HH + cg * 32);
        const ulonglong2* b2p = (const ulonglong2*)(g_B2 + (size_t)d * HH + cg * 32);
        u64 u[16];
#pragma unroll
        for (int i = 0; i < 8; i++) {
            ulonglong2 va = b1p[i], vb = b2p[i];
            u[2 * i]     = f2add(va.x, vb.x);
            u[2 * i + 1] = f2add(va.y, vb.y);
        }
#pragma unroll 1
        for (int r = 0; r < 16; r++) {
            float ev = sm[E2_EXT + r * 64 + e];
            u64 ev2 = pk(ev, ev);
            const ulonglong2* wp = (const ulonglong2*)(sm + E2_WEXT + r * 128 + cg * 32);
#pragma unroll
            for (int i = 0; i < 8; i++) {
                ulonglong2 w = wp[i];
                u[2 * i]     = f2fma(ev2, w.x, u[2 * i]);
                u[2 * i + 1] = f2fma(ev2, w.y, u[2 * i + 1]);
            }
        }
#pragma unroll
        for (int i = 0; i < 16; i++) {
            float a, b; upk(a, b, u[i]);
            sm[E2_C1T + (cg * 32 + 2 * i) * 64 + e]     = silu_f(a);
            sm[E2_C1T + (cg * 32 + 2 * i + 1) * 64 + e] = silu_f(b);
        }
    }
    __syncthreads();

    // GEMM: c2 = c1 @ Wx_w2 + b (adjacent cols, weights from L1)
    int cidx = tid & 63, eg = tid >> 6;
    int c0 = 2 * cidx;
    u64 acc0[8], acc1[8];
    {
        float2 bb = *(const float2*)(sm + E2_B2 + c0);
        u64 p0 = pk(bb.x, bb.x), p1 = pk(bb.y, bb.y);
#pragma unroll
        for (int q = 0; q < 8; q++) { acc0[q] = p0; acc1[q] = p1; }
    }
#pragma unroll 4
    for (int k = 0; k < 128; k++) {
        float2 w = __ldg((const float2*)(Wx_w2 + k * 128 + c0));
        u64 ww0 = pk(w.x, w.x), ww1 = pk(w.y, w.y);
        const ulonglong2* mp = (const ulonglong2*)(sm + E2_C1T + k * 64 + eg * 16);
        ulonglong2 m0 = mp[0], m1 = mp[1], m2 = mp[2], m3 = mp[3];
        acc0[0] = f2fma(m0.x, ww0, acc0[0]); acc1[0] = f2fma(m0.x, ww1, acc1[0]);
        acc0[1] = f2fma(m0.y, ww0, acc0[1]); acc1[1] = f2fma(m0.y, ww1, acc1[1]);
        acc0[2] = f2fma(m1.x, ww0, acc0[2]); acc1[2] = f2fma(m1.x, ww1, acc1[2]);
        acc0[3] = f2fma(m1.y, ww0, acc0[3]); acc1[3] = f2fma(m1.y, ww1, acc1[3]);
        acc0[4] = f2fma(m2.x, ww0, acc0[4]); acc1[4] = f2fma(m2.x, ww1, acc1[4]);
        acc0[5] = f2fma(m2.y, ww0, acc0[5]); acc1[5] = f2fma(m2.y, ww1, acc1[5]);
        acc0[6] = f2fma(m3.x, ww0, acc0[6]); acc1[6] = f2fma(m3.x, ww1, acc1[6]);
        acc0[7] = f2fma(m3.y, ww0, acc0[7]); acc1[7] = f2fma(m3.y, ww1, acc1[7]);
    }

    // coord-weight partial
    {
        float2 w3 = *(const float2*)(sm + E2_WX3 + c0);
        u64 pc[8];
#pragma unroll
        for (int q = 0; q < 8; q++) {
            float a, b, p0, p1;
            upk(a, b, acc0[q]);
            p0 = silu_f(a) * w3.x; p1 = silu_f(b) * w3.x;
            upk(a, b, acc1[q]);
            p0 += silu_f(a) * w3.y; p1 += silu_f(b) * w3.y;
            pc[q] = pk(p0, p1);
        }
#pragma unroll
        for (int msk = 16; msk > 0; msk >>= 1)
#pragma unroll
            for (int q = 0; q < 8; q++)
                pc[q] = f2add(pc[q], __shfl_xor_sync(0xffffffffu, pc[q], msk));
        if ((tid & 31) == 0) {
            int warp = tid >> 5;
            u64* red = (u64*)(sm + E2_RED);
#pragma unroll
            for (int q = 0; q < 8; q++) red[warp * 8 + q] = pc[q];
        }
    }
    __syncthreads();

    if (tid < ET) {
        int e = tid, eg2 = e >> 4, q16 = e & 15;
        float s = sm[E2_RED + (2 * eg2) * 16 + q16] + sm[E2_RED + (2 * eg2 + 1) * 16 + q16];
        float cw = tanhf(s) * 2.5f;
        int d = sDst[e];
        atomicAdd(&g_coord[d * 3 + 0], sm[E2_DIFFN + 0 * 64 + e] * cw);
        atomicAdd(&g_coord[d * 3 + 1], sm[E2_DIFFN + 1 * 64 + e] * cw);
        atomicAdd(&g_coord[d * 3 + 2], sm[E2_DIFFN + 2 * 64 + e] * cw);
    }
}

// ---------------- phi_h + output assembly ----------------
#define NODE_SMEM_FLOATS (256*128 + 128*128 + 128 + 128 + 256*PH_PAD + 128*PH_PAD)
#define NODE_SMEM_BYTES  (NODE_SMEM_FLOATS * 4)

__global__ __launch_bounds__(512, 1)
void node_out_kernel(const float* __restrict__ h, const float* __restrict__ x,
                     const float* __restrict__ Wh_w1, const float* __restrict__ Wh_b1,
                     const float* __restrict__ Wh_w2, const float* __restrict__ Wh_b2,
                     float* __restrict__ out)
{
    extern __shared__ float sm[];
    float* sW1   = sm;
    float* sW2   = sW1 + 256 * 128;
    float* sB1   = sW2 + 128 * 128;
    float* sB2   = sB1 + 128;
    float* sInT  = sB2 + 128;
    float* sHidT = sInT + 256 * PH_PAD;

    int tid = threadIdx.x;
    {
        const float4* s1 = (const float4*)Wh_w1;
        float4* d1 = (float4*)sW1;
        for (int i = tid; i < 8192; i += 512) d1[i] = s1[i];
        const float4* s2 = (const float4*)Wh_w2;
        float4* d2 = (float4*)sW2;
        for (int i = tid; i < 4096; i += 512) d2[i] = s2[i];
    }
    if (tid < 128) { sB1[tid] = Wh_b1[tid]; sB2[tid] = Wh_b2[tid]; }

    int col = tid & 127, grp = tid >> 7;
    int jb = grp * 4;

    for (int tile = blockIdx.x; tile < NN / PH_NB; tile += gridDim.x) {
        int n0 = tile * PH_NB;
        __syncthreads();
        for (int i = tid; i < PH_NB * HH; i += 512) {
            int j = i >> 7, k = i & 127;
            int n = n0 + j;
            sInT[k * PH_PAD + j]        = h[(size_t)n * HH + k];
            sInT[(HH + k) * PH_PAD + j] = g_msg[(size_t)n * HH + k];
        }
        __syncthreads();

        u64 acc[2];
        {
            float b = sB1[col]; u64 bb = pk(b, b);
            acc[0] = bb; acc[1] = bb;
        }
#pragma unroll 4
        for (int k = 0; k < 256; k++) {
            float w = sW1[k * 128 + col];
            u64 ww = pk(w, w);
            const u64* p = (const u64*)(sInT + k * PH_PAD + jb);
            acc[0] = f2fma(p[0], ww, acc[0]);
            acc[1] = f2fma(p[1], ww, acc[1]);
        }
        {
            float a, b;
            upk(a, b, acc[0]);
            sHidT[col * PH_PAD + jb + 0] = silu_f(a);
            sHidT[col * PH_PAD + jb + 1] = silu_f(b);
            upk(a, b, acc[1]);
            sHidT[col * PH_PAD + jb + 2] = silu_f(a);
            sHidT[col * PH_PAD + jb + 3] = silu_f(b);
        }
        __syncthreads();

        u64 acc2[2];
        {
            float b = sB2[col]; u64 bb = pk(b, b);
            acc2[0] = bb; acc2[1] = bb;
        }
#pragma unroll 4
        for (int k = 0; k < 128; k++) {
            float w = sW2[k * 128 + col];
            u64 ww = pk(w, w);
            const u64* p = (const u64*)(sHidT + k * PH_PAD + jb);
            acc2[0] = f2fma(p[0], ww, acc2[0]);
            acc2[1] = f2fma(p[1], ww, acc2[1]);
        }
        {
            float a, b;
            upk(a, b, acc2[0]);
            out[(size_t)(n0 + jb + 0) * HH + col] = h[(size_t)(n0 + jb + 0) * HH + col] + a;
            out[(size_t)(n0 + jb + 1) * HH + col] = h[(size_t)(n0 + jb + 1) * HH + col] + b;
            upk(a, b, acc2[1]);
            out[(size_t)(n0 + jb + 2) * HH + col] = h[(size_t)(n0 + jb + 2) * HH + col] + a;
            out[(size_t)(n0 + jb + 3) * HH + col] = h[(size_t)(n0 + jb + 3) * HH + col] + b;
        }
        if (tid < PH_NB * 3) {
            int n = n0 + tid / 3, c = tid % 3;
            out[(size_t)NN * HH + n * 3 + c] = x[n * 3 + c] + g_coord[n * 3 + c];
        }
    }
}

// ---------------- launch ----------------
extern "C" void kernel_launch(void* const* d_in, const int* in_sizes, int n_in,
                              void* d_out, int out_size) {
    const float* h         = (const float*)d_in[0];
    const float* x         = (const float*)d_in[1];
    const void*  ei        = d_in[2];
    const float* edge_attr = (const float*)d_in[3];
    const float* t_emb     = (const float*)d_in[4];
    const float* We_w1     = (const float*)d_in[5];
    const float* We_b1     = (const float*)d_in[6];
    const float* We_w2     = (const float*)d_in[7];
    const float* We_b2     = (const float*)d_in[8];
    const float* Watt_w    = (const float*)d_in[9];
    const float* Watt_b    = (const float*)d_in[10];
    const float* Wx_w1     = (const float*)d_in[11];
    const float* Wx_b1     = (const float*)d_in[12];
    const float* Wx_w2     = (const float*)d_in[13];
    const float* Wx_b2     = (const float*)d_in[14];
    const float* Wx_w3     = (const float*)d_in[15];
    const float* Wh_w1     = (const float*)d_in[16];
    const float* Wh_b1     = (const float*)d_in[17];
    const float* Wh_w2     = (const float*)d_in[18];
    const float* Wh_b2     = (const float*)d_in[19];
    float* out = (float*)d_out;

    int nsm = 148;
    cudaDeviceGetAttribute(&nsm, cudaDevAttrMultiProcessorCount, 0);

    cudaFuncSetAttribute(e1_kernel, cudaFuncAttributeMaxDynamicSharedMemorySize, E1_BYTES);
    cudaFuncSetAttribute(e2_kernel, cudaFuncAttributeMaxDynamicSharedMemorySize, E2_BYTES);
    cudaFuncSetAttribute(node_out_kernel, cudaFuncAttributeMaxDynamicSharedMemorySize, NODE_SMEM_BYTES);

    int eblocks = NE / ET;

    detect_kernel<<<1, 256>>>(ei);
    precompute_kernel<<<NN / PC_NB, 128>>>(h, t_emb, We_w1, We_b1, Wx_w1, Wx_b1);
    e1_kernel<<<eblocks, 256, E1_BYTES>>>(x, ei, edge_attr, We_w1, We_w2, We_b2, Watt_w, Watt_b);
    e2_kernel<<<eblocks, 256, E2_BYTES>>>(x, ei, edge_attr, Wx_w1, Wx_w2, Wx_b2, Wx_w3);
    node_out_kernel<<<nsm, 512, NODE_SMEM_BYTES>>>(h, x, Wh_w1, Wh_b1, Wh_w2, Wh_b2, out);
}